// round 3
// baseline (speedup 1.0000x reference)
#include <cuda_runtime.h>

#define N_  32
#define C_  3
#define H_  224
#define W_  224
#define T_  17
#define HW_ (H_ * W_)

#define TILE_O 32
#define ROWS_I 45            // float rows stored   (0..44)
#define COLS_I 45            // float cols stored   (0..44)
#define EPR    44            // float2 entries/row  (entry c = (f[c], f[c+1]))
#define CH_STR (ROWS_I * EPR)   // 1980 entries per channel

// identical fp expression everywhere -> monotone bbox guarantee
#define MAP_X(wf, hf) __fadd_rn(__fsub_rn(__fmul_rn(c,(wf)), __fmul_rn(s,(hf))), HALF)
#define MAP_Y(wf, hf) __fadd_rn(__fadd_rn(__fmul_rn(s,(wf)), __fmul_rn(c,(hf))), HALF)

__global__ __launch_bounds__(256) void rot_tile4_kernel(
    const float* __restrict__ x,       // (N, C, H, W)
    const float* __restrict__ thetas,  // (N, T)
    float* __restrict__ out)           // (N, T, C, H, W)
{
    __shared__ float2 tile2[C_ * CH_STR];   // 47,520 B

    const int nt  = blockIdx.y;
    const int n   = nt / T_;
    const int tid = threadIdx.x;
    const int tx0 = (blockIdx.x % 7) * TILE_O;
    const int ty0 = (blockIdx.x / 7) * TILE_O;

    float s, c;
    sincosf(thetas[nt], &s, &c);
    const float HALF = 111.5f;

    // ---- input bbox from tile corners (same expression as per-pixel map) ----
    const float wfa = (float)tx0 - HALF;
    const float wfb = (float)(tx0 + TILE_O - 1) - HALF;
    const float hfa = (float)ty0 - HALF;
    const float hfb = (float)(ty0 + TILE_O - 1) - HALF;

    const float min_ix = fminf(fminf(MAP_X(wfa,hfa), MAP_X(wfb,hfa)),
                               fminf(MAP_X(wfa,hfb), MAP_X(wfb,hfb)));
    const float min_iy = fminf(fminf(MAP_Y(wfa,hfa), MAP_Y(wfb,hfa)),
                               fminf(MAP_Y(wfa,hfb), MAP_Y(wfb,hfb)));
    const int gx0 = (int)floorf(min_ix);
    const int gy0 = (int)floorf(min_iy);

    const bool interior = (gx0 >= 0) && (gy0 >= 0) &&
                          (gx0 + COLS_I - 1 <= W_ - 1) &&
                          (gy0 + ROWS_I - 1 <= H_ - 1);

    const int img_base = (n * C_) * HW_;

    // ---- cooperative tile fill (duplicated float2 layout) ----
    if (interior) {
#pragma unroll
        for (int ch = 0; ch < C_; ch++) {
            const float* img = x + img_base + ch * HW_ + gy0 * W_ + gx0;
            float* tf = (float*)(tile2 + ch * CH_STR);
            for (int i = tid; i < ROWS_I * COLS_I; i += 256) {
                const int r  = i / COLS_I;
                const int cc = i - r * COLS_I;
                const float v = __ldg(img + r * W_ + cc);
                float* row = tf + r * (2 * EPR);
                if (cc < COLS_I - 1) row[2 * cc] = v;       // entry cc .x
                if (cc > 0)          row[2 * cc - 1] = v;   // entry cc-1 .y
            }
        }
    } else {
#pragma unroll
        for (int ch = 0; ch < C_; ch++) {
            const float* img = x + img_base + ch * HW_;
            float* tf = (float*)(tile2 + ch * CH_STR);
            for (int i = tid; i < ROWS_I * COLS_I; i += 256) {
                const int r  = i / COLS_I;
                const int cc = i - r * COLS_I;
                const int gr = min(max(gy0 + r,  0), H_ - 1);
                const int gc = min(max(gx0 + cc, 0), W_ - 1);
                const float v = __ldg(img + gr * W_ + gc);
                float* row = tf + r * (2 * EPR);
                if (cc < COLS_I - 1) row[2 * cc] = v;
                if (cc > 0)          row[2 * cc - 1] = v;
            }
        }
    }
    __syncthreads();

    // ---- per-thread: 1 row, 4 consecutive output cols, 3 channels ----
    const int row  = tid >> 3;            // 0..31
    const int col4 = (tid & 7) * 4;       // 0,4,...,28

    const float hf = (float)(ty0 + row) - HALF;

    float w00[4], w01[4], w10[4], w11[4];
    int   addr[4];

    if (interior) {
#pragma unroll
        for (int j = 0; j < 4; j++) {
            const float wf = (float)(tx0 + col4 + j) - HALF;
            const float ix = MAP_X(wf, hf);
            const float iy = MAP_Y(wf, hf);
            const float ix0f = floorf(ix);
            const float iy0f = floorf(iy);
            const float fx = ix - ix0f;
            const float fy = iy - iy0f;
            const float gxw = 1.0f - fx;
            const float gyw = 1.0f - fy;
            w00[j] = gyw * gxw;  w01[j] = gyw * fx;
            w10[j] = fy  * gxw;  w11[j] = fy  * fx;
            addr[j] = ((int)iy0f - gy0) * EPR + ((int)ix0f - gx0);
        }
    } else {
#pragma unroll
        for (int j = 0; j < 4; j++) {
            const float wf = (float)(tx0 + col4 + j) - HALF;
            const float ix = MAP_X(wf, hf);
            const float iy = MAP_Y(wf, hf);
            const float ix0f = floorf(ix);
            const float iy0f = floorf(iy);
            const float fx = ix - ix0f;
            const float fy = iy - iy0f;
            const float gxw = 1.0f - fx;
            const float gyw = 1.0f - fy;
            const int ix0 = (int)ix0f;
            const int iy0 = (int)iy0f;
            const float vx0 = (ix0 >= 0  && ix0 < W_)     ? 1.0f : 0.0f;
            const float vx1 = (ix0 >= -1 && ix0 < W_ - 1) ? 1.0f : 0.0f;
            const float vy0 = (iy0 >= 0  && iy0 < H_)     ? 1.0f : 0.0f;
            const float vy1 = (iy0 >= -1 && iy0 < H_ - 1) ? 1.0f : 0.0f;
            w00[j] = gyw * gxw * (vy0 * vx0);
            w01[j] = gyw * fx  * (vy0 * vx1);
            w10[j] = fy  * gxw * (vy1 * vx0);
            w11[j] = fy  * fx  * (vy1 * vx1);
            const int cs = min(max(ix0 - gx0, 0), EPR - 1);
            const int rs = min(max(iy0 - gy0, 0), ROWS_I - 2);
            addr[j] = rs * EPR + cs;
        }
    }

    const unsigned out_px = (unsigned)(nt * C_) * HW_
                          + (unsigned)(ty0 + row) * W_ + (tx0 + col4);

#pragma unroll
    for (int ch = 0; ch < C_; ch++) {
        const float2* t = tile2 + ch * CH_STR;
        float4 r4;
        float* rp = (float*)&r4;
#pragma unroll
        for (int j = 0; j < 4; j++) {
            const float2 top = t[addr[j]];
            const float2 bot = t[addr[j] + EPR];
            rp[j] = top.x * w00[j] + top.y * w01[j]
                  + bot.x * w10[j] + bot.y * w11[j];
        }
        *reinterpret_cast<float4*>(out + out_px + (unsigned)ch * HW_) = r4;
    }
}

extern "C" void kernel_launch(void* const* d_in, const int* in_sizes, int n_in,
                              void* d_out, int out_size) {
    const float* x      = (const float*)d_in[0];
    const float* thetas = (const float*)d_in[1];
    float* out          = (float*)d_out;

    dim3 block(256);
    dim3 grid(7 * 7, N_ * T_);   // 49 tiles x 544 rotations
    rot_tile4_kernel<<<grid, block>>>(x, thetas, out);
}

// round 4
// speedup vs baseline: 2.8583x; 2.8583x over previous
#include <cuda_runtime.h>

#define N_  32
#define C_  3
#define H_  224
#define W_  224
#define T_  17
#define HW_ (H_ * W_)
#define TILE_O 32

#define TROWS 47          // tile rows/cols stored (44-span + 1 tap + 2 guard)
#define TSTR  49          // padded row stride (odd -> bank-friendly)
#define CH_STR (TROWS * TSTR)   // 2303 floats per channel

// identical fp expression for corners and pixels
#define MAP_X(wf, hf) __fadd_rn(__fsub_rn(__fmul_rn(c,(wf)), __fmul_rn(s,(hf))), 111.5f)
#define MAP_Y(wf, hf) __fadd_rn(__fadd_rn(__fmul_rn(s,(wf)), __fmul_rn(c,(hf))), 111.5f)

__global__ __launch_bounds__(256, 8) void rot_tile_v4_kernel(
    const float* __restrict__ x,       // (N, C, H, W)
    const float* __restrict__ thetas,  // (N, T)
    float* __restrict__ out)           // (N, T, C, H, W)
{
    __shared__ float tile[C_ * CH_STR];   // 27,636 B

    const int nt  = blockIdx.y;
    const int n   = nt / T_;
    const int tid = threadIdx.x;
    const int tx0 = (blockIdx.x % 7) * TILE_O;
    const int ty0 = (blockIdx.x / 7) * TILE_O;

    float s, c;
    sincosf(thetas[nt], &s, &c);

    // ---- input bbox from tile corners (same fp expr as per-pixel map) ----
    const float wfa = (float)tx0 - 111.5f;
    const float wfb = (float)(tx0 + TILE_O - 1) - 111.5f;
    const float hfa = (float)ty0 - 111.5f;
    const float hfb = (float)(ty0 + TILE_O - 1) - 111.5f;

    const float min_ix = fminf(fminf(MAP_X(wfa,hfa), MAP_X(wfb,hfa)),
                               fminf(MAP_X(wfa,hfb), MAP_X(wfb,hfb)));
    const float min_iy = fminf(fminf(MAP_Y(wfa,hfa), MAP_Y(wfb,hfa)),
                               fminf(MAP_Y(wfa,hfb), MAP_Y(wfb,hfb)));
    const int gx0 = (int)floorf(min_ix);
    const int gy0 = (int)floorf(min_iy);
    const int ox0 = gx0 - 1;      // tile origin incl. 1-texel guard
    const int oy0 = gy0 - 1;

    // interior: every tap of every pixel lies inside the image
    const bool interior = (gx0 >= 0) && (gy0 >= 0) &&
                          (gx0 + 44 <= W_ - 1) && (gy0 + 44 <= H_ - 1);

    const int img_base = (n * C_) * HW_;

    // ---- fill: warp-per-row, always clamped (uniform, cheap) ----
    {
        const int lane = tid & 31;
        const int warp = tid >> 5;
        const int gc0 = min(max(ox0 + lane, 0), W_ - 1);
        const int gc1 = min(max(ox0 + lane + 32, 0), W_ - 1);
        const bool have2 = (lane + 32) < TROWS;   // lanes 0..14
        for (int r = warp; r < TROWS; r += 8) {
            const int gr = min(max(oy0 + r, 0), H_ - 1);
            const float* src = x + img_base + gr * W_;
            float* dst = tile + r * TSTR;
#pragma unroll
            for (int ch = 0; ch < C_; ch++) {
                dst[ch * CH_STR + lane] = __ldg(src + ch * HW_ + gc0);
                if (have2)
                    dst[ch * CH_STR + lane + 32] = __ldg(src + ch * HW_ + gc1);
            }
        }
    }
    __syncthreads();

    // ---- compute: thread = (row tid>>4, col pair (tid&15)*2), 2 row-steps ----
    const int orow = tid >> 4;           // 0..15
    const int ocol = (tid & 15) * 2;     // 0..30

    const float wf0 = (float)(tx0 + ocol) - 111.5f;
    const unsigned obase = (unsigned)nt * (C_ * HW_)
                         + (unsigned)(ty0 + orow) * W_ + (unsigned)(tx0 + ocol);

#pragma unroll
    for (int j = 0; j < 2; j++) {
        const int row = orow + 16 * j;
        const float hf = (float)(ty0 + row) - 111.5f;

        // pixel a (ocol), pixel b (ocol+1) — b via incremental add
        const float ixa = MAP_X(wf0, hf);
        const float iya = MAP_Y(wf0, hf);
        const float ixb = __fadd_rn(ixa, c);
        const float iyb = __fadd_rn(iya, s);

        float wA00, wA01, wA10, wA11, wB00, wB01, wB10, wB11;
        int aA, aB;

        {
            const float fxa = ixa - floorf(ixa);
            const float fya = iya - floorf(iya);
            const float fxb = ixb - floorf(ixb);
            const float fyb = iyb - floorf(iyb);
            const int ix0a = (int)floorf(ixa), iy0a = (int)floorf(iya);
            const int ix0b = (int)floorf(ixb), iy0b = (int)floorf(iyb);

            const float gxa = 1.0f - fxa, gya = 1.0f - fya;
            const float gxb = 1.0f - fxb, gyb = 1.0f - fyb;

            if (interior) {
                wA00 = gya * gxa; wA01 = gya * fxa; wA10 = fya * gxa; wA11 = fya * fxa;
                wB00 = gyb * gxb; wB01 = gyb * fxb; wB10 = fyb * gxb; wB11 = fyb * fxb;
                aA = (iy0a - oy0) * TSTR + (ix0a - ox0);
                aB = (iy0b - oy0) * TSTR + (ix0b - ox0);
            } else {
                const float vxa0 = (ix0a >= 0  && ix0a < W_)     ? 1.0f : 0.0f;
                const float vxa1 = (ix0a >= -1 && ix0a < W_ - 1) ? 1.0f : 0.0f;
                const float vya0 = (iy0a >= 0  && iy0a < H_)     ? 1.0f : 0.0f;
                const float vya1 = (iy0a >= -1 && iy0a < H_ - 1) ? 1.0f : 0.0f;
                const float vxb0 = (ix0b >= 0  && ix0b < W_)     ? 1.0f : 0.0f;
                const float vxb1 = (ix0b >= -1 && ix0b < W_ - 1) ? 1.0f : 0.0f;
                const float vyb0 = (iy0b >= 0  && iy0b < H_)     ? 1.0f : 0.0f;
                const float vyb1 = (iy0b >= -1 && iy0b < H_ - 1) ? 1.0f : 0.0f;
                wA00 = gya * gxa * (vya0 * vxa0); wA01 = gya * fxa * (vya0 * vxa1);
                wA10 = fya * gxa * (vya1 * vxa0); wA11 = fya * fxa * (vya1 * vxa1);
                wB00 = gyb * gxb * (vyb0 * vxb0); wB01 = gyb * fxb * (vyb0 * vxb1);
                wB10 = fyb * gxb * (vyb1 * vxb0); wB11 = fyb * fxb * (vyb1 * vxb1);
                aA = min(max(iy0a - oy0, 0), TROWS - 2) * TSTR
                   + min(max(ix0a - ox0, 0), TROWS - 2);
                aB = min(max(iy0b - oy0, 0), TROWS - 2) * TSTR
                   + min(max(ix0b - ox0, 0), TROWS - 2);
            }
        }

        const unsigned ob = obase + (unsigned)(16 * j) * W_;

#pragma unroll
        for (int ch = 0; ch < C_; ch++) {
            const float* t = tile + ch * CH_STR;
            float2 r2;
            r2.x = t[aA]        * wA00 + t[aA + 1]        * wA01
                 + t[aA + TSTR] * wA10 + t[aA + TSTR + 1] * wA11;
            r2.y = t[aB]        * wB00 + t[aB + 1]        * wB01
                 + t[aB + TSTR] * wB10 + t[aB + TSTR + 1] * wB11;
            *reinterpret_cast<float2*>(out + ob + (unsigned)ch * HW_) = r2;
        }
    }
}

extern "C" void kernel_launch(void* const* d_in, const int* in_sizes, int n_in,
                              void* d_out, int out_size) {
    const float* x      = (const float*)d_in[0];
    const float* thetas = (const float*)d_in[1];
    float* out          = (float*)d_out;

    dim3 block(256);
    dim3 grid(7 * 7, N_ * T_);   // 49 tiles x 544 rotations
    rot_tile_v4_kernel<<<grid, block>>>(x, thetas, out);
}

// round 5
// speedup vs baseline: 3.0328x; 1.0610x over previous
#include <cuda_runtime.h>
#include <cuda_fp16.h>

#define N_  32
#define C_  3
#define H_  224
#define W_  224
#define T_  17
#define HW_ (H_ * W_)
#define TILE_O 32

#define TROWS 47                 // tile rows (44-span + tap + guard)
#define ENT_MAX 45               // max valid entry index per row (entries 0..45)
#define TSTR  47                 // entry stride per row (odd -> bank-friendly)
#define CH_STR (TROWS * TSTR)    // 2209 half2-entries per channel

// identical fp expression for corners and pixels (monotone bbox guarantee)
#define MAP_X(wf, hf) __fadd_rn(__fsub_rn(__fmul_rn(c,(wf)), __fmul_rn(s,(hf))), 111.5f)
#define MAP_Y(wf, hf) __fadd_rn(__fadd_rn(__fmul_rn(s,(wf)), __fmul_rn(c,(hf))), 111.5f)

__global__ __launch_bounds__(256, 8) void rot_tile_h2_kernel(
    const float* __restrict__ x,       // (N, C, H, W)
    const float* __restrict__ thetas,  // (N, T)
    float* __restrict__ out)           // (N, T, C, H, W)
{
    __shared__ __half2 tile[C_ * CH_STR];   // 26,508 B

    const int nt  = blockIdx.y;
    const int n   = nt / T_;
    const int tid = threadIdx.x;
    const int tx0 = (blockIdx.x % 7) * TILE_O;
    const int ty0 = (blockIdx.x / 7) * TILE_O;

    float s, c;
    sincosf(thetas[nt], &s, &c);

    // ---- input bbox from tile corners ----
    const float wfa = (float)tx0 - 111.5f;
    const float wfb = (float)(tx0 + TILE_O - 1) - 111.5f;
    const float hfa = (float)ty0 - 111.5f;
    const float hfb = (float)(ty0 + TILE_O - 1) - 111.5f;

    const float min_ix = fminf(fminf(MAP_X(wfa,hfa), MAP_X(wfb,hfa)),
                               fminf(MAP_X(wfa,hfb), MAP_X(wfb,hfb)));
    const float min_iy = fminf(fminf(MAP_Y(wfa,hfa), MAP_Y(wfb,hfa)),
                               fminf(MAP_Y(wfa,hfb), MAP_Y(wfb,hfb)));
    const int gx0 = (int)floorf(min_ix);
    const int gy0 = (int)floorf(min_iy);
    const int ox0 = gx0 - 1;      // tile origin incl. guard texel
    const int oy0 = gy0 - 1;

    const bool interior = (gx0 >= 0) && (gy0 >= 0) &&
                          (gx0 + 44 <= W_ - 1) && (gy0 + 44 <= H_ - 1);

    const int img_base = (n * C_) * HW_;

    // ---- fill: warp-per-row; entry e = (half(f[e]), half(f[e+1])) ----
    {
        const int lane = tid & 31;
        const int warp = tid >> 5;
        const int gA0 = min(max(ox0 + lane,      0), W_ - 1);
        const int gA1 = min(max(ox0 + lane + 1,  0), W_ - 1);
        const int gB0 = min(max(ox0 + lane + 32, 0), W_ - 1);
        const int gB1 = min(max(ox0 + lane + 33, 0), W_ - 1);
        const bool have2 = (lane + 32) <= ENT_MAX;   // lanes 0..13
        for (int r = warp; r < TROWS; r += 8) {
            const int gr = min(max(oy0 + r, 0), H_ - 1);
            const float* src = x + img_base + gr * W_;
            __half2* dst = tile + r * TSTR;
#pragma unroll
            for (int ch = 0; ch < C_; ch++) {
                const float* sc = src + ch * HW_;
                dst[ch * CH_STR + lane] =
                    __floats2half2_rn(__ldg(sc + gA0), __ldg(sc + gA1));
                if (have2)
                    dst[ch * CH_STR + lane + 32] =
                        __floats2half2_rn(__ldg(sc + gB0), __ldg(sc + gB1));
            }
        }
    }
    __syncthreads();

    // ---- compute: thread = (row tid>>4, col pair), 2 row-steps ----
    const int orow = tid >> 4;           // 0..15
    const int ocol = (tid & 15) * 2;     // 0..30

    const float wf0 = (float)(tx0 + ocol) - 111.5f;
    const unsigned obase = (unsigned)nt * (C_ * HW_)
                         + (unsigned)(ty0 + orow) * W_ + (unsigned)(tx0 + ocol);

#pragma unroll
    for (int j = 0; j < 2; j++) {
        const int row = orow + 16 * j;
        const float hf = (float)(ty0 + row) - 111.5f;

        const float ixa = MAP_X(wf0, hf);
        const float iya = MAP_Y(wf0, hf);
        const float ixb = __fadd_rn(ixa, c);
        const float iyb = __fadd_rn(iya, s);

        float wA00, wA01, wA10, wA11, wB00, wB01, wB10, wB11;
        int aA, aB;
        {
            const float fxa = ixa - floorf(ixa);
            const float fya = iya - floorf(iya);
            const float fxb = ixb - floorf(ixb);
            const float fyb = iyb - floorf(iyb);
            const int ix0a = (int)floorf(ixa), iy0a = (int)floorf(iya);
            const int ix0b = (int)floorf(ixb), iy0b = (int)floorf(iyb);

            const float gxa = 1.0f - fxa, gya = 1.0f - fya;
            const float gxb = 1.0f - fxb, gyb = 1.0f - fyb;

            if (interior) {
                wA00 = gya * gxa; wA01 = gya * fxa; wA10 = fya * gxa; wA11 = fya * fxa;
                wB00 = gyb * gxb; wB01 = gyb * fxb; wB10 = fyb * gxb; wB11 = fyb * fxb;
                aA = (iy0a - oy0) * TSTR + (ix0a - ox0);
                aB = (iy0b - oy0) * TSTR + (ix0b - ox0);
            } else {
                const float vxa0 = (ix0a >= 0  && ix0a < W_)     ? 1.0f : 0.0f;
                const float vxa1 = (ix0a >= -1 && ix0a < W_ - 1) ? 1.0f : 0.0f;
                const float vya0 = (iy0a >= 0  && iy0a < H_)     ? 1.0f : 0.0f;
                const float vya1 = (iy0a >= -1 && iy0a < H_ - 1) ? 1.0f : 0.0f;
                const float vxb0 = (ix0b >= 0  && ix0b < W_)     ? 1.0f : 0.0f;
                const float vxb1 = (ix0b >= -1 && ix0b < W_ - 1) ? 1.0f : 0.0f;
                const float vyb0 = (iy0b >= 0  && iy0b < H_)     ? 1.0f : 0.0f;
                const float vyb1 = (iy0b >= -1 && iy0b < H_ - 1) ? 1.0f : 0.0f;
                wA00 = gya * gxa * (vya0 * vxa0); wA01 = gya * fxa * (vya0 * vxa1);
                wA10 = fya * gxa * (vya1 * vxa0); wA11 = fya * fxa * (vya1 * vxa1);
                wB00 = gyb * gxb * (vyb0 * vxb0); wB01 = gyb * fxb * (vyb0 * vxb1);
                wB10 = fyb * gxb * (vyb1 * vxb0); wB11 = fyb * fxb * (vyb1 * vxb1);
                aA = min(max(iy0a - oy0, 0), TROWS - 2) * TSTR
                   + min(max(ix0a - ox0, 0), ENT_MAX);
                aB = min(max(iy0b - oy0, 0), TROWS - 2) * TSTR
                   + min(max(ix0b - ox0, 0), ENT_MAX);
            }
        }

        const unsigned ob = obase + (unsigned)(16 * j) * W_;

#pragma unroll
        for (int ch = 0; ch < C_; ch++) {
            const __half2* t = tile + ch * CH_STR;
            const float2 tA0 = __half22float2(t[aA]);          // (t00, t01)
            const float2 tA1 = __half22float2(t[aA + TSTR]);   // (t10, t11)
            const float2 tB0 = __half22float2(t[aB]);
            const float2 tB1 = __half22float2(t[aB + TSTR]);
            float2 r2;
            r2.x = tA0.x * wA00 + tA0.y * wA01 + tA1.x * wA10 + tA1.y * wA11;
            r2.y = tB0.x * wB00 + tB0.y * wB01 + tB1.x * wB10 + tB1.y * wB11;
            *reinterpret_cast<float2*>(out + ob + (unsigned)ch * HW_) = r2;
        }
    }
}

extern "C" void kernel_launch(void* const* d_in, const int* in_sizes, int n_in,
                              void* d_out, int out_size) {
    const float* x      = (const float*)d_in[0];
    const float* thetas = (const float*)d_in[1];
    float* out          = (float*)d_out;

    dim3 block(256);
    dim3 grid(7 * 7, N_ * T_);   // 49 tiles x 544 rotations
    rot_tile_h2_kernel<<<grid, block>>>(x, thetas, out);
}

// round 6
// speedup vs baseline: 3.0747x; 1.0138x over previous
#include <cuda_runtime.h>

#define N_  32
#define C_  3
#define H_  224
#define W_  224
#define T_  17
#define HW_ (H_ * W_)
#define TILE_O 32

#define TROWS 45
#define TCOLS 48                    // floats per row = 12 float4
#define CH_STR (TROWS * TCOLS)      // 2160 floats per channel

// identical fp expression for corners and pixels -> exact monotone bbox
#define MAP_X(wf, hf) __fadd_rn(__fsub_rn(__fmul_rn(c,(wf)), __fmul_rn(s,(hf))), 111.5f)
#define MAP_Y(wf, hf) __fadd_rn(__fadd_rn(__fmul_rn(s,(wf)), __fmul_rn(c,(hf))), 111.5f)

__global__ __launch_bounds__(256, 8) void rot_tile_v6_kernel(
    const float* __restrict__ x,       // (N, C, H, W)
    const float* __restrict__ thetas,  // (N, T)
    float* __restrict__ out)           // (N, T, C, H, W)
{
    __shared__ float tile[C_ * CH_STR];   // 25,920 B

    const int nt  = blockIdx.y;
    const int n   = nt / T_;
    const int tid = threadIdx.x;
    const int tx0 = (blockIdx.x % 7) * TILE_O;
    const int ty0 = (blockIdx.x / 7) * TILE_O;

    float s, c;
    sincosf(thetas[nt], &s, &c);

    // ---- input bbox from tile corners ----
    const float wfa = (float)tx0 - 111.5f;
    const float wfb = (float)(tx0 + TILE_O - 1) - 111.5f;
    const float hfa = (float)ty0 - 111.5f;
    const float hfb = (float)(ty0 + TILE_O - 1) - 111.5f;

    const float min_ix = fminf(fminf(MAP_X(wfa,hfa), MAP_X(wfb,hfa)),
                               fminf(MAP_X(wfa,hfb), MAP_X(wfb,hfb)));
    const float min_iy = fminf(fminf(MAP_Y(wfa,hfa), MAP_Y(wfb,hfa)),
                               fminf(MAP_Y(wfa,hfb), MAP_Y(wfb,hfb)));
    const int gx0 = (int)floorf(min_ix);
    const int gy0 = (int)floorf(min_iy);
    const int a0  = gx0 & ~3;          // 16B-aligned col origin (rounds toward -inf)

    // ix0 in [gx0, gx0+43] (+1 tap), col = ix0-a0 <= 46+1 <= 47 < 48
    const bool interior = (gy0 >= 0) && (gy0 + TROWS - 1 <= H_ - 1) &&
                          (a0  >= 0) && (a0  + TCOLS - 1 <= W_ - 1);

    const int img_base = (n * C_) * HW_;
    const int lane = tid & 31;
    const int warp = tid >> 5;

    // ---- tile fill ----
    if (interior) {
        // 12 lanes x float4 per row per channel, all aligned
        if (lane < 12) {
            for (int r = warp; r < TROWS; r += 8) {
                const float* src = x + img_base + (gy0 + r) * W_ + a0 + 4 * lane;
                float* dst = tile + r * TCOLS + 4 * lane;
#pragma unroll
                for (int ch = 0; ch < C_; ch++) {
                    *reinterpret_cast<float4*>(dst + ch * CH_STR) =
                        *reinterpret_cast<const float4*>(src + ch * HW_);
                }
            }
        }
    } else {
        const int gc0 = min(max(a0 + lane,      0), W_ - 1);
        const int gc1 = min(max(a0 + lane + 32, 0), W_ - 1);
        const bool have2 = lane < (TCOLS - 32);   // lanes 0..15
        for (int r = warp; r < TROWS; r += 8) {
            const int gr = min(max(gy0 + r, 0), H_ - 1);
            const float* src = x + img_base + gr * W_;
            float* dst = tile + r * TCOLS;
#pragma unroll
            for (int ch = 0; ch < C_; ch++) {
                dst[ch * CH_STR + lane] = __ldg(src + ch * HW_ + gc0);
                if (have2)
                    dst[ch * CH_STR + lane + 32] = __ldg(src + ch * HW_ + gc1);
            }
        }
    }
    __syncthreads();

    // ---- compute: thread = (row tid>>4, col pair), 2 row-steps ----
    const int orow = tid >> 4;           // 0..15
    const int ocol = (tid & 15) * 2;     // 0..30

    const float wf0 = (float)(tx0 + ocol) - 111.5f;
    const unsigned obase = (unsigned)nt * (C_ * HW_)
                         + (unsigned)(ty0 + orow) * W_ + (unsigned)(tx0 + ocol);

#pragma unroll
    for (int j = 0; j < 2; j++) {
        const int row = orow + 16 * j;
        const float hf = (float)(ty0 + row) - 111.5f;

        const float ixa = MAP_X(wf0, hf);
        const float iya = MAP_Y(wf0, hf);
        const float ixb = __fadd_rn(ixa, c);
        const float iyb = __fadd_rn(iya, s);

        float wA00, wA01, wA10, wA11, wB00, wB01, wB10, wB11;
        int aA, aB;
        {
            const float fxa = ixa - floorf(ixa);
            const float fya = iya - floorf(iya);
            const float fxb = ixb - floorf(ixb);
            const float fyb = iyb - floorf(iyb);
            const int ix0a = (int)floorf(ixa), iy0a = (int)floorf(iya);
            const int ix0b = (int)floorf(ixb), iy0b = (int)floorf(iyb);

            const float gxa = 1.0f - fxa, gya = 1.0f - fya;
            const float gxb = 1.0f - fxb, gyb = 1.0f - fyb;

            if (interior) {
                wA00 = gya * gxa; wA01 = gya * fxa; wA10 = fya * gxa; wA11 = fya * fxa;
                wB00 = gyb * gxb; wB01 = gyb * fxb; wB10 = fyb * gxb; wB11 = fyb * fxb;
                aA = (iy0a - gy0) * TCOLS + (ix0a - a0);
                aB = (iy0b - gy0) * TCOLS + (ix0b - a0);
            } else {
                const float vxa0 = (ix0a >= 0  && ix0a < W_)     ? 1.0f : 0.0f;
                const float vxa1 = (ix0a >= -1 && ix0a < W_ - 1) ? 1.0f : 0.0f;
                const float vya0 = (iy0a >= 0  && iy0a < H_)     ? 1.0f : 0.0f;
                const float vya1 = (iy0a >= -1 && iy0a < H_ - 1) ? 1.0f : 0.0f;
                const float vxb0 = (ix0b >= 0  && ix0b < W_)     ? 1.0f : 0.0f;
                const float vxb1 = (ix0b >= -1 && ix0b < W_ - 1) ? 1.0f : 0.0f;
                const float vyb0 = (iy0b >= 0  && iy0b < H_)     ? 1.0f : 0.0f;
                const float vyb1 = (iy0b >= -1 && iy0b < H_ - 1) ? 1.0f : 0.0f;
                wA00 = gya * gxa * (vya0 * vxa0); wA01 = gya * fxa * (vya0 * vxa1);
                wA10 = fya * gxa * (vya1 * vxa0); wA11 = fya * fxa * (vya1 * vxa1);
                wB00 = gyb * gxb * (vyb0 * vxb0); wB01 = gyb * fxb * (vyb0 * vxb1);
                wB10 = fyb * gxb * (vyb1 * vxb0); wB11 = fyb * fxb * (vyb1 * vxb1);
                aA = min(max(iy0a - gy0, 0), TROWS - 2) * TCOLS
                   + min(max(ix0a - a0,  0), TCOLS - 2);
                aB = min(max(iy0b - gy0, 0), TROWS - 2) * TCOLS
                   + min(max(ix0b - a0,  0), TCOLS - 2);
            }
        }

        const unsigned ob = obase + (unsigned)(16 * j) * W_;

#pragma unroll
        for (int ch = 0; ch < C_; ch++) {
            const float* t = tile + ch * CH_STR;
            float2 r2;
            r2.x = t[aA]         * wA00 + t[aA + 1]         * wA01
                 + t[aA + TCOLS] * wA10 + t[aA + TCOLS + 1] * wA11;
            r2.y = t[aB]         * wB00 + t[aB + 1]         * wB01
                 + t[aB + TCOLS] * wB10 + t[aB + TCOLS + 1] * wB11;
            *reinterpret_cast<float2*>(out + ob + (unsigned)ch * HW_) = r2;
        }
    }
}

extern "C" void kernel_launch(void* const* d_in, const int* in_sizes, int n_in,
                              void* d_out, int out_size) {
    const float* x      = (const float*)d_in[0];
    const float* thetas = (const float*)d_in[1];
    float* out          = (float*)d_out;

    dim3 block(256);
    dim3 grid(7 * 7, N_ * T_);   // 49 tiles x 544 rotations
    rot_tile_v6_kernel<<<grid, block>>>(x, thetas, out);
}